// round 14
// baseline (speedup 1.0000x reference)
#include <cuda_runtime.h>
#include <cuda_bf16.h>
#include <cstdint>

// LSTM_22763326669221 — round 14: gate-split warps, B fragments register-
// resident. R13 (555us) was L1-bound (91.4%): 56 of 63 LDSM per warp-step
// re-fetched loop-invariant B. Now each warp owns 32 gate columns (its 8
// units x 4 gates) for the CTA's 16 shared elements: B frags = 56 regs
// loaded ONCE. Column order: ntile q = gate type, within-tile col = unit
// -> lane-local epilogue (all 4 gates of units 2t,2t+1 in one lane).
// h/x staged through the shared A buffer with 2 syncthreads per step.

#define SEQB   3
#define BATCH  524288
#define FOUT   3
#define THREADS 128

typedef uint32_t u32;

__device__ __forceinline__ u32 smem_u32(const void* p) {
    u32 a;
    asm("{ .reg .u64 t; cvta.to.shared.u64 t, %1; cvt.u32.u64 %0, t; }"
        : "=r"(a) : "l"(p));
    return a;
}
__device__ __forceinline__ float tanh_hw(float x) {
    float r; asm("tanh.approx.f32 %0, %1;" : "=f"(r) : "f"(x)); return r;
}
__device__ __forceinline__ float sigmoid_hw(float x) {
    return fmaf(0.5f, tanh_hw(0.5f * x), 0.5f);
}
// pack: v0 -> low bf16, v1 -> high bf16
__device__ __forceinline__ u32 pk_bf2(float v0, float v1) {
    u32 d; asm("cvt.rn.bf16x2.f32 %0, %1, %2;" : "=r"(d) : "f"(v1), "f"(v0));
    return d;
}
__device__ __forceinline__ void split2(float v0, float v1, u32& hi, u32& lo) {
    hi = pk_bf2(v0, v1);
    float r0 = v0 - __uint_as_float(hi << 16);
    float r1 = v1 - __uint_as_float(hi & 0xffff0000u);
    lo = pk_bf2(r0, r1);
}
__device__ __forceinline__ void sts32(u32 addr, u32 v) {
    asm volatile("st.shared.b32 [%0], %1;" :: "r"(addr), "r"(v) : "memory");
}

#define LDSM4(r0, r1, r2, r3, a) \
    asm volatile("ldmatrix.sync.aligned.m8n8.x4.shared.b16 {%0,%1,%2,%3}, [%4];" \
                 : "=r"(r0), "=r"(r1), "=r"(r2), "=r"(r3) : "r"(a))

#define MMA(dp, a0, a1, a2, a3, b0, b1) \
    asm volatile("mma.sync.aligned.m16n8k16.row.col.f32.bf16.bf16.f32 " \
                 "{%0,%1,%2,%3},{%4,%5,%6,%7},{%8,%9},{%0,%1,%2,%3};" \
                 : "+f"((dp)[0]), "+f"((dp)[1]), "+f"((dp)[2]), "+f"((dp)[3]) \
                 : "r"(a0), "r"(a1), "r"(a2), "r"(a3), "r"(b0), "r"(b1))

// Blocked 8x8-tile offset helpers (14 ktiles per row-tile):
//   A: rows 16 (2 rtiles), entry (r, k):
#define AOFF(r, k) (((((r) >> 3) * 14 + ((k) >> 3)) * 128) + (((r) & 7) * 16) + (((k) & 7) * 2))
//   B: 16 ntiles x 14 ktiles, entry (col c, k):
#define BOFF(c, k) (((((c) >> 3) * 14 + ((k) >> 3)) * 128) + (((c) & 7) * 16) + (((k) & 7) * 2))

// K layout (112 = 14 k8-tiles):
//   seg0 k0-35  : A=hi [x0,x1,1,pad,h0..h31], B=W hi
//   seg1 k36-71 : A=hi (dup),                 B=W lo
//   seg2 k72-107: A=lo residuals,             B=W hi
//   k108-111: zero pad.
// Gate column map: global col c = 32w + 8q + ct -> weight row q*32 + 8w + ct.

__global__ void __launch_bounds__(THREADS)
lstm_mma_kernel(const float* __restrict__ x,
                const float* __restrict__ W_ih,
                const float* __restrict__ W_hh,
                const float* __restrict__ b_ih,
                const float* __restrict__ b_hh,
                const float* __restrict__ W_fc,
                const float* __restrict__ b_fc,
                float* __restrict__ out) {
    __shared__ __align__(16) char sB[16 * 14 * 128];   // 28672 B, built once
    __shared__ __align__(16) char sA[2 * 14 * 128];    // 3584 B, per-step A
    __shared__ float2 sPart[4][16];                    // FC partials per warp
    __shared__ float2 sWin[16][3];                     // x window per element
    __shared__ float  sFC[2][32];
    __shared__ float  sFCb[2];

    const int tid  = threadIdx.x;
    const int w    = tid >> 5;
    const int lane = tid & 31;
    const int g    = lane >> 2;
    const int t    = lane & 3;
    const u32 sB_a = smem_u32(sB);
    const u32 sA_a = smem_u32(sA);

    // ---- zero smem ----
    for (int i = tid; i < (16 * 14 * 128) / 4; i += THREADS)
        reinterpret_cast<u32*>(sB)[i] = 0;
    for (int i = tid; i < (2 * 14 * 128) / 4; i += THREADS)
        reinterpret_cast<u32*>(sA)[i] = 0;
    __syncthreads();

    // ---- build B (thread = gate column c) ----
    {
        const int c = tid;
        const int n = ((c >> 3) & 3) * 32 + (c >> 5) * 8 + (c & 7);
        for (int s = 0; s < 36; s++) {
            float wv = (s == 0) ? W_ih[2 * n]
                     : (s == 1) ? W_ih[2 * n + 1]
                     : (s == 2) ? (b_ih[n] + b_hh[n])
                     : (s == 3) ? 0.0f
                     : W_hh[n * 32 + (s - 4)];
            __nv_bfloat16 hb = __float2bfloat16(wv);
            float hf = __bfloat162float(hb);
            uint16_t hbits = __bfloat16_as_ushort(hb);
            uint16_t lbits = __bfloat16_as_ushort(__float2bfloat16(wv - hf));
            *reinterpret_cast<uint16_t*>(sB + BOFF(c, s))      = hbits;
            *reinterpret_cast<uint16_t*>(sB + BOFF(c, 36 + s)) = lbits;
            *reinterpret_cast<uint16_t*>(sB + BOFF(c, 72 + s)) = hbits;
        }
    }
    if (tid < 64) sFC[tid >> 5][tid & 31] = W_fc[tid];
    if (tid < 2)  sFCb[tid] = b_fc[tid];
    if (tid < 16) {
        const int r = tid;
        const int e = blockIdx.x * 16 + r;
        const float2* x2 = reinterpret_cast<const float2*>(x);
        float2 v0 = x2[e], v1 = x2[BATCH + e], v2 = x2[2 * BATCH + e];
        sWin[r][0] = v0; sWin[r][1] = v1; sWin[r][2] = v2;
        // bias columns (A == 1) at k=2 (seg0) and k=38 (seg1); residual 0.
        *reinterpret_cast<uint16_t*>(sA + AOFF(r, 2))  = 0x3F80;
        *reinterpret_cast<uint16_t*>(sA + AOFF(r, 38)) = 0x3F80;
        // stage x for t=0
        u32 xh, xl; split2(v0.x, v0.y, xh, xl);
        sts32(sA_a + AOFF(r, 0),  xh);
        sts32(sA_a + AOFF(r, 36), xh);
        sts32(sA_a + AOFF(r, 72), xl);
    }
    __syncthreads();

    // ---- load B fragments once: warp w owns ntiles 4w..4w+3 ----
    const int msel = lane >> 3, rowin = lane & 7;
    u32 bfr[7][8];
    {
        const u32 base = sB_a +
            (u32)((((4 * w + (msel >> 1)) * 14 + (msel & 1)) * 128) + rowin * 16);
#pragma unroll
        for (int m = 0; m < 7; m++) {
            LDSM4(bfr[m][0], bfr[m][1], bfr[m][2], bfr[m][3], base + m * 256);
            LDSM4(bfr[m][4], bfr[m][5], bfr[m][6], bfr[m][7],
                  base + 2 * 14 * 128 + m * 256);
        }
    }
    const u32 addrA = sA_a +
        (u32)((((msel & 1) * 14 + (msel >> 1)) * 128) + rowin * 16);

    // h staging addresses: unit pair k-slot k0 = 4 + 8w + 2t
    const int k0 = 4 + 8 * w + 2 * t;
    const u32 hg0s0 = sA_a + AOFF(g, k0);
    const u32 hg0s1 = sA_a + AOFF(g, k0 + 36);
    const u32 hg0s2 = sA_a + AOFF(g, k0 + 72);
    const u32 hg1s0 = sA_a + AOFF(g + 8, k0);
    const u32 hg1s1 = sA_a + AOFF(g + 8, k0 + 36);
    const u32 hg1s2 = sA_a + AOFF(g + 8, k0 + 72);

    float c4[4] = {0.0f, 0.0f, 0.0f, 0.0f};
    float2* o2 = reinterpret_cast<float2*>(out);

#pragma unroll 1
    for (int f = 0; f < FOUT; f++) {
#pragma unroll 1
        for (int tt = 0; tt < SEQB; tt++) {
            // A fragments (same for all warps; broadcast loads)
            u32 a[7][4];
#pragma unroll
            for (int m = 0; m < 7; m++)
                LDSM4(a[m][0], a[m][1], a[m][2], a[m][3], addrA + m * 256);

            float d[4][4];
#pragma unroll
            for (int q = 0; q < 4; q++)
#pragma unroll
                for (int i2 = 0; i2 < 4; i2++) d[q][i2] = 0.0f;
#pragma unroll
            for (int m = 0; m < 7; m++) {
                MMA(d[0], a[m][0], a[m][1], a[m][2], a[m][3], bfr[m][0], bfr[m][1]);
                MMA(d[1], a[m][0], a[m][1], a[m][2], a[m][3], bfr[m][2], bfr[m][3]);
                MMA(d[2], a[m][0], a[m][1], a[m][2], a[m][3], bfr[m][4], bfr[m][5]);
                MMA(d[3], a[m][0], a[m][1], a[m][2], a[m][3], bfr[m][6], bfr[m][7]);
            }
            __syncthreads();   // all warps done reading A

            // lane-local epilogue: d[gate][inst], inst: (row g,u0),(g,u1),(g+8,u0),(g+8,u1)
            float h4[4];
#pragma unroll
            for (int i2 = 0; i2 < 4; i2++) {
                float zi = d[0][i2], zf = d[1][i2], zg = d[2][i2], zo = d[3][i2];
                float cn = fmaf(sigmoid_hw(zf), c4[i2], sigmoid_hw(zi) * tanh_hw(zg));
                c4[i2] = cn;
                h4[i2] = sigmoid_hw(zo) * tanh_hw(cn);
            }
            // stage h (next step's A)
            u32 hi, lo;
            split2(h4[0], h4[1], hi, lo);
            sts32(hg0s0, hi); sts32(hg0s1, hi); sts32(hg0s2, lo);
            split2(h4[2], h4[3], hi, lo);
            sts32(hg1s0, hi); sts32(hg1s1, hi); sts32(hg1s2, lo);

            if (tt < 2) {
                if (tid < 16) {   // stage x for next t
                    float2 xp = sWin[tid][tt + 1];
                    u32 xh, xl; split2(xp.x, xp.y, xh, xl);
                    sts32(sA_a + AOFF(tid, 0),  xh);
                    sts32(sA_a + AOFF(tid, 36), xh);
                    sts32(sA_a + AOFF(tid, 72), xl);
                }
            } else {
                // FC partials over this warp's 8 units (f32 h, pre-split)
                const int j0 = 8 * w + 2 * t;
                float F00 = sFC[0][j0], F01 = sFC[0][j0 + 1];
                float F10 = sFC[1][j0], F11 = sFC[1][j0 + 1];
                float pA0 = h4[0] * F00 + h4[1] * F01;
                float pA1 = h4[0] * F10 + h4[1] * F11;
                float pB0 = h4[2] * F00 + h4[3] * F01;
                float pB1 = h4[2] * F10 + h4[3] * F11;
                pA0 += __shfl_xor_sync(0xffffffffu, pA0, 1);
                pA1 += __shfl_xor_sync(0xffffffffu, pA1, 1);
                pB0 += __shfl_xor_sync(0xffffffffu, pB0, 1);
                pB1 += __shfl_xor_sync(0xffffffffu, pB1, 1);
                pA0 += __shfl_xor_sync(0xffffffffu, pA0, 2);
                pA1 += __shfl_xor_sync(0xffffffffu, pA1, 2);
                pB0 += __shfl_xor_sync(0xffffffffu, pB0, 2);
                pB1 += __shfl_xor_sync(0xffffffffu, pB1, 2);
                if (t == 0) {
                    sPart[w][g]     = make_float2(pA0, pA1);
                    sPart[w][g + 8] = make_float2(pB0, pB1);
                }
                __syncthreads();
                if (tid < 16) {
                    const int r = tid;
                    float o0 = sFCb[0], o1 = sFCb[1];
#pragma unroll
                    for (int ww = 0; ww < 4; ww++) {
                        float2 p = sPart[ww][r];
                        o0 += p.x; o1 += p.y;
                    }
                    o2[f * BATCH + blockIdx.x * 16 + r] = make_float2(o0, o1);
                    // window: data <- [d2, d1, out]; stage x for next t=0
                    float2 nd0 = sWin[r][2];
                    sWin[r][0] = nd0;
                    sWin[r][2] = make_float2(o0, o1);
                    u32 xh, xl; split2(nd0.x, nd0.y, xh, xl);
                    sts32(sA_a + AOFF(r, 0),  xh);
                    sts32(sA_a + AOFF(r, 36), xh);
                    sts32(sA_a + AOFF(r, 72), xl);
                }
            }
            __syncthreads();   // A staged for next step
        }
    }
}

extern "C" void kernel_launch(void* const* d_in, const int* in_sizes, int n_in,
                              void* d_out, int out_size) {
    const float* x    = (const float*)d_in[0];
    const float* W_ih = (const float*)d_in[1];
    const float* W_hh = (const float*)d_in[2];
    const float* b_ih = (const float*)d_in[3];
    const float* b_hh = (const float*)d_in[4];
    const float* W_fc = (const float*)d_in[5];
    const float* b_fc = (const float*)d_in[6];
    float* out = (float*)d_out;

    dim3 grid(BATCH / 16);   // 32768 CTAs, each: 4 warps x 16 shared elements
    lstm_mma_kernel<<<grid, THREADS>>>(x, W_ih, W_hh, b_ih, b_hh, W_fc, b_fc, out);
}